// round 8
// baseline (speedup 1.0000x reference)
#include <cuda_runtime.h>

#define NN 100000
#define NE 1600000
#define FULLMASK 0xffffffffu

// ---------------- static device scratch (no allocations allowed) -------------
static __device__ __align__(256) float d_bufH[(size_t)NN * 256]; // h0 | h1 (JK concat)
static __device__ __align__(256) float d_bufY[(size_t)NN * 128]; // neighbor-transform
static __device__ __align__(256) float d_bufZ[(size_t)NN * 128]; // self-transform
static __device__ __align__(256) float d_bufF[(size_t)NN * 128]; // JK projection
static __device__ int d_deg[NN];
static __device__ int d_off[NN + 1];
static __device__ int d_cur[NN];
static __device__ int d_csr[NE];
static __device__ int d_is64;  // 1 if edge_index buffer is int64, 0 if int32

// ---------------- edge dtype detection ---------------------------------------
// JAX x64 is disabled by default: jnp.int64 edge_index is silently int32.
// Misreading int32 data as int64 fuses two node ids into one garbage index ->
// global atomic into the shared aperture -> trap 717. Detect the layout:
// for little-endian int64 values < 2^31, every odd 32-bit word is 0.
__global__ void detect_dtype_kernel(const int* __restrict__ ei32, int nwords) {
    __shared__ int red[8];
    int tid = threadIdx.x;
    int v = 0;
    for (int i = tid; i < 4096; i += 256) {
        int idx = 2 * i + 1;
        if (idx < nwords) v |= ei32[idx];
    }
#pragma unroll
    for (int m = 16; m >= 1; m >>= 1) v |= __shfl_xor_sync(FULLMASK, v, m);
    if ((tid & 31) == 0) red[tid >> 5] = v;
    __syncthreads();
    if (tid == 0) {
        int a = 0;
#pragma unroll
        for (int i = 0; i < 8; i++) a |= red[i];
        d_is64 = (a == 0) ? 1 : 0;
    }
}

__device__ __forceinline__ int load_edge(const void* eiv, size_t idx) {
    if (d_is64) return (int)((const long long*)eiv)[idx];
    return ((const int*)eiv)[idx];
}

// ---------------- CSR build --------------------------------------------------
__global__ void zero_deg_kernel(int n) {
    int i = blockIdx.x * blockDim.x + threadIdx.x;
    if (i < n) d_deg[i] = 0;
}

__global__ void count_deg_kernel(const void* __restrict__ eiv, int E, int N) {
    int i = blockIdx.x * blockDim.x + threadIdx.x;
    if (i < E) {
        int dst = load_edge(eiv, (size_t)E + i);
        if ((unsigned)dst < (unsigned)N) atomicAdd(&d_deg[dst], 1);
    }
}

// single-block exclusive scan of d_deg -> d_off (and d_cur cursor copy)
__global__ void scan_deg_kernel(int n) {
    __shared__ int wsum[32];
    __shared__ int carry_s;
    int tid = threadIdx.x, lane = tid & 31, wid = tid >> 5;
    if (tid == 0) carry_s = 0;
    __syncthreads();
    for (int base = 0; base < n; base += 1024) {
        int idx = base + tid;
        int v = (idx < n) ? d_deg[idx] : 0;
        int incl = v;
#pragma unroll
        for (int off = 1; off < 32; off <<= 1) {
            int t = __shfl_up_sync(FULLMASK, incl, off);
            if (lane >= off) incl += t;
        }
        if (lane == 31) wsum[wid] = incl;
        __syncthreads();
        if (wid == 0) {
            int s = wsum[lane];
            int si = s;
#pragma unroll
            for (int off = 1; off < 32; off <<= 1) {
                int t = __shfl_up_sync(FULLMASK, si, off);
                if (lane >= off) si += t;
            }
            wsum[lane] = si - s;  // exclusive prefix of warp sums
        }
        __syncthreads();
        int excl = incl - v + wsum[wid];
        int c = carry_s;
        if (idx < n) { d_off[idx] = c + excl; d_cur[idx] = c + excl; }
        __syncthreads();
        if (tid == 1023) carry_s = c + excl + v;  // chunk inclusive total
        __syncthreads();
    }
    if (threadIdx.x == 0) d_off[n] = carry_s;
}

__global__ void fill_csr_kernel(const void* __restrict__ eiv, int E, int N) {
    int i = blockIdx.x * blockDim.x + threadIdx.x;
    if (i < E) {
        int src = load_edge(eiv, (size_t)i);
        int dst = load_edge(eiv, (size_t)E + i);
        if ((unsigned)dst < (unsigned)N) {
            if ((unsigned)src >= (unsigned)N) src = 0;  // safety clamp
            int p = atomicAdd(&d_cur[dst], 1);
            if ((unsigned)p < (unsigned)NE) d_csr[p] = src;
        }
    }
}

// ---------------- SGEMM: C[N,128] = A[N,K](lda) @ W[K,128], f32x2 FMA --------
// Aext == nullptr -> A = d_bufH (device-global scratch); cdst selects C buffer.
__global__ __launch_bounds__(256) void sgemm128_kernel(
    const float* __restrict__ Aext, int lda, int K,
    const float* __restrict__ W, int cdst, int N) {
    __shared__ __align__(16) float As[16 * 132];  // [k][row], padded stride
    __shared__ __align__(16) float Bs[16 * 128];  // [k][col]
    const float* A = Aext ? Aext : (const float*)d_bufH;
    float* C = (cdst == 0) ? (float*)d_bufY : (cdst == 1) ? (float*)d_bufZ
                                                          : (float*)d_bufF;
    int n0 = blockIdx.x * 128;
    int tid = threadIdx.x;
    int tr = (tid >> 4) * 8;  // row offset of 8x8 microtile
    int tc = (tid & 15) * 8;  // col offset
    unsigned long long acc[8][4];
#pragma unroll
    for (int i = 0; i < 8; i++)
#pragma unroll
        for (int j = 0; j < 4; j++) acc[i][j] = 0ull;

    for (int k0 = 0; k0 < K; k0 += 16) {
        __syncthreads();
        // stage A tile (128 rows x 16 k) transposed into As[k][row]
#pragma unroll
        for (int it = 0; it < 2; it++) {
            int s = tid + it * 256;
            int row = s >> 2;
            int kq = (s & 3) * 4;
            float4 v = make_float4(0.f, 0.f, 0.f, 0.f);
            int gr = n0 + row;
            if (gr < N) v = *(const float4*)(A + (size_t)gr * lda + k0 + kq);
            As[(kq + 0) * 132 + row] = v.x;
            As[(kq + 1) * 132 + row] = v.y;
            As[(kq + 2) * 132 + row] = v.z;
            As[(kq + 3) * 132 + row] = v.w;
        }
        // stage W tile (16 k x 128 cols)
#pragma unroll
        for (int it = 0; it < 2; it++) {
            int s = tid + it * 256;
            int kr = s >> 5;
            int c4 = (s & 31) * 4;
            *(float4*)(Bs + kr * 128 + c4) =
                *(const float4*)(W + (size_t)(k0 + kr) * 128 + c4);
        }
        __syncthreads();
#pragma unroll
        for (int k = 0; k < 16; k++) {
            float4 a0 = *(const float4*)(As + k * 132 + tr);
            float4 a1 = *(const float4*)(As + k * 132 + tr + 4);
            ulonglong2 b0 = *(const ulonglong2*)(Bs + k * 128 + tc);
            ulonglong2 b1v = *(const ulonglong2*)(Bs + k * 128 + tc + 4);
            float av[8] = {a0.x, a0.y, a0.z, a0.w, a1.x, a1.y, a1.z, a1.w};
            unsigned long long bv[4] = {b0.x, b0.y, b1v.x, b1v.y};
#pragma unroll
            for (int i = 0; i < 8; i++) {
                unsigned long long ad;
                unsigned int ai = __float_as_uint(av[i]);
                asm("mov.b64 %0, {%1, %1};" : "=l"(ad) : "r"(ai));
#pragma unroll
                for (int j = 0; j < 4; j++)
                    asm("fma.rn.f32x2 %0, %1, %2, %0;"
                        : "+l"(acc[i][j]) : "l"(ad), "l"(bv[j]));
            }
        }
    }
#pragma unroll
    for (int i = 0; i < 8; i++) {
        int gr = n0 + tr + i;
        if (gr < N) {
            float2 p0 = *(float2*)&acc[i][0];
            float2 p1 = *(float2*)&acc[i][1];
            float2 p2 = *(float2*)&acc[i][2];
            float2 p3 = *(float2*)&acc[i][3];
            *(float4*)(C + (size_t)gr * 128 + tc)     = make_float4(p0.x, p0.y, p1.x, p1.y);
            *(float4*)(C + (size_t)gr * 128 + tc + 4) = make_float4(p2.x, p2.y, p3.x, p3.y);
        }
    }
}

// ---------------- aggregate(mean) + bias + self + LayerNorm + ReLU -----------
// reads d_bufY (neighbor feats) + d_bufZ (self feats), writes d_bufH + coloff
__global__ void agg_ln_kernel(const float* __restrict__ bn, const float* __restrict__ g,
                              const float* __restrict__ be, int coloff, int N) {
    const float* y = (const float*)d_bufY;
    const float* z = (const float*)d_bufZ;
    float* hout = (float*)d_bufH + coloff;
    int w = (blockIdx.x * blockDim.x + threadIdx.x) >> 5;
    int lane = threadIdx.x & 31;
    if (w >= N) return;
    int s = d_off[w], e = d_off[w + 1];
    float4 acc = make_float4(0.f, 0.f, 0.f, 0.f);
    int i = s;
    for (; i + 2 <= e; i += 2) {
        int s0 = d_csr[i], s1 = d_csr[i + 1];
        float4 v0 = *(const float4*)(y + (size_t)s0 * 128 + lane * 4);
        float4 v1 = *(const float4*)(y + (size_t)s1 * 128 + lane * 4);
        acc.x += v0.x + v1.x; acc.y += v0.y + v1.y;
        acc.z += v0.z + v1.z; acc.w += v0.w + v1.w;
    }
    if (i < e) {
        int s0 = d_csr[i];
        float4 v0 = *(const float4*)(y + (size_t)s0 * 128 + lane * 4);
        acc.x += v0.x; acc.y += v0.y; acc.z += v0.z; acc.w += v0.w;
    }
    int deg = e - s;
    float inv = 1.f / (float)(deg > 0 ? deg : 1);
    float4 zb = *(const float4*)(z + (size_t)w * 128 + lane * 4);
    float4 bn4 = *(const float4*)(bn + lane * 4);
    float4 t;
    t.x = fmaf(acc.x, inv, bn4.x + zb.x);
    t.y = fmaf(acc.y, inv, bn4.y + zb.y);
    t.z = fmaf(acc.z, inv, bn4.z + zb.z);
    t.w = fmaf(acc.w, inv, bn4.w + zb.w);
    float sum = t.x + t.y + t.z + t.w;
#pragma unroll
    for (int m = 16; m >= 1; m >>= 1) sum += __shfl_xor_sync(FULLMASK, sum, m);
    float mu = sum * (1.f / 128.f);
    float dx = t.x - mu, dy = t.y - mu, dz = t.z - mu, dw = t.w - mu;
    float sq = dx * dx + dy * dy + dz * dz + dw * dw;
#pragma unroll
    for (int m = 16; m >= 1; m >>= 1) sq += __shfl_xor_sync(FULLMASK, sq, m);
    float r = rsqrtf(sq * (1.f / 128.f) + 1e-5f);
    float4 g4 = *(const float4*)(g + lane * 4);
    float4 be4 = *(const float4*)(be + lane * 4);
    float4 h;
    h.x = fmaxf(fmaf(dx * r, g4.x, be4.x), 0.f);
    h.y = fmaxf(fmaf(dy * r, g4.y, be4.y), 0.f);
    h.z = fmaxf(fmaf(dz * r, g4.z, be4.z), 0.f);
    h.w = fmaxf(fmaf(dw * r, g4.w, be4.w), 0.f);
    *(float4*)(hout + (size_t)w * 256 + lane * 4) = h;
}

// ---------------- MLP head: out = relu((F+bjk)@W1+b1)@W2+b2 ------------------
__global__ __launch_bounds__(256) void head_kernel(
    const float* __restrict__ bjk,
    const float* __restrict__ W1, const float* __restrict__ b1,
    const float* __restrict__ W2, const float* __restrict__ b2,
    float* __restrict__ out, int N) {
    __shared__ __align__(16) float W1T[32 * 132];  // [j][k], padded stride
    __shared__ __align__(16) float W2s[32 * 16];
    __shared__ __align__(16) float b1s[32];
    __shared__ __align__(16) float b2s[16];
    __shared__ __align__(16) float bjs[128];
    const float* F = (const float*)d_bufF;
    int tid = threadIdx.x;
    for (int s = tid; s < 128 * 32; s += 256) {
        int k = s >> 5, j = s & 31;
        W1T[j * 132 + k] = W1[s];
    }
    for (int s = tid; s < 512; s += 256) W2s[s] = W2[s];
    if (tid < 32) b1s[tid] = b1[tid];
    if (tid < 16) b2s[tid] = b2[tid];
    if (tid < 128) bjs[tid] = bjk[tid];
    __syncthreads();
    int lane = tid & 31;
    int wg = (blockIdx.x * 256 + tid) >> 5;
    int nw = (gridDim.x * 256) >> 5;
    for (int node = wg; node < N; node += nw) {
        float4 f = *(const float4*)(F + (size_t)node * 128 + lane * 4);
        float4 bj = *(const float4*)(bjs + lane * 4);
        f.x += bj.x; f.y += bj.y; f.z += bj.z; f.w += bj.w;
        float p[32];
#pragma unroll
        for (int j = 0; j < 32; j++) {
            float4 wv = *(const float4*)(W1T + j * 132 + lane * 4);
            p[j] = f.x * wv.x + f.y * wv.y + f.z * wv.z + f.w * wv.w;
        }
#pragma unroll
        for (int m = 16; m >= 1; m >>= 1) {
#pragma unroll
            for (int j = 0; j < 32; j++) p[j] += __shfl_xor_sync(FULLMASK, p[j], m);
        }
        if (lane < 16) {
            float o = b2s[lane];
#pragma unroll
            for (int j = 0; j < 32; j++) {
                float hj = fmaxf(p[j] + b1s[j], 0.f);
                o = fmaf(hj, W2s[j * 16 + lane], o);
            }
            out[(size_t)node * 16 + lane] = o;
        }
    }
}

// ---------------- launch: kernel launches ONLY (graph-capturable) ------------
extern "C" void kernel_launch(void* const* d_in, const int* in_sizes, int n_in,
                              void* d_out, int out_size) {
    const float* x     = (const float*)d_in[0];
    const void*  eiv   = d_in[1];  // int32 or int64 edge_index, detected on-device
    const float* W_nl0 = (const float*)d_in[2];
    const float* b_nl0 = (const float*)d_in[3];
    const float* W_r0  = (const float*)d_in[4];
    const float* W_nl1 = (const float*)d_in[5];
    const float* b_nl1 = (const float*)d_in[6];
    const float* W_r1  = (const float*)d_in[7];
    const float* g0    = (const float*)d_in[8];
    const float* be0   = (const float*)d_in[9];
    const float* g1    = (const float*)d_in[10];
    const float* be1   = (const float*)d_in[11];
    const float* W_jk  = (const float*)d_in[12];
    const float* b_jk  = (const float*)d_in[13];
    const float* W_h1  = (const float*)d_in[14];
    const float* b_h1  = (const float*)d_in[15];
    const float* W_h2  = (const float*)d_in[16];
    const float* b_h2  = (const float*)d_in[17];
    float* out = (float*)d_out;

    int N = in_sizes[0] / 256;
    int E = in_sizes[1] / 2;
    if (N > NN) N = NN;
    if (E > NE) E = NE;

    int gN = (N + 255) / 256;
    int gE = (E + 255) / 256;
    int gGemm = (N + 127) / 128;
    int gAgg = (N + 7) / 8;  // 8 warps per 256-thread block

    // edge dtype detection + CSR build (structure reused by both conv layers)
    detect_dtype_kernel<<<1, 256>>>((const int*)eiv, in_sizes[1]);
    zero_deg_kernel<<<gN, 256>>>(N);
    count_deg_kernel<<<gE, 256>>>(eiv, E, N);
    scan_deg_kernel<<<1, 1024>>>(N);
    fill_csr_kernel<<<gE, 256>>>(eiv, E, N);

    // layer 0: y0 = x@W_nl0 -> bufY, z0 = x@W_r0 -> bufZ, agg+LN+ReLU -> h0
    sgemm128_kernel<<<gGemm, 256>>>(x, 256, 256, W_nl0, 0, N);
    sgemm128_kernel<<<gGemm, 256>>>(x, 256, 256, W_r0, 1, N);
    agg_ln_kernel<<<gAgg, 256>>>(b_nl0, g0, be0, 0, N);

    // layer 1: y1 = h0@W_nl1 -> bufY, z1 = h0@W_r1 -> bufZ, agg+LN+ReLU -> h1
    sgemm128_kernel<<<gGemm, 256>>>(nullptr, 256, 128, W_nl1, 0, N);
    sgemm128_kernel<<<gGemm, 256>>>(nullptr, 256, 128, W_r1, 1, N);
    agg_ln_kernel<<<gAgg, 256>>>(b_nl1, g1, be1, 128, N);

    // JK projection: bufF = [h0|h1] @ W_jk   (bias folded into head kernel)
    sgemm128_kernel<<<gGemm, 256>>>(nullptr, 256, 256, W_jk, 2, N);

    // MLP head
    head_kernel<<<592, 256>>>(b_jk, W_h1, b_h1, W_h2, b_h2, out, N);
}

// round 11
// speedup vs baseline: 1.1248x; 1.1248x over previous
#include <cuda_runtime.h>

#define NN 100000
#define NE 1600000
#define FULLMASK 0xffffffffu

// ---------------- static device scratch (no allocations allowed) -------------
static __device__ __align__(256) float d_bufH[(size_t)NN * 256]; // h0 | h1 (JK concat)
static __device__ __align__(256) float d_bufY[(size_t)NN * 128]; // neighbor-transform
static __device__ __align__(256) float d_bufZ[(size_t)NN * 128]; // self-transform
static __device__ __align__(256) float d_bufF[(size_t)NN * 128]; // JK projection
static __device__ int d_deg[NN];
static __device__ int d_off[NN + 1];
static __device__ int d_cur[NN];
static __device__ int d_csr[NE];
static __device__ int d_part[128];      // per-block scan partials
static __device__ int d_partscan[128];  // exclusive-scanned partials
static __device__ int d_is64;           // 1 if edge_index is int64, 0 if int32

// ---------------- edge dtype detection ---------------------------------------
// JAX x64 is disabled by default: jnp.int64 edge_index is silently int32.
// For little-endian int64 values < 2^31, every odd 32-bit word is 0.
__global__ void detect_dtype_kernel(const int* __restrict__ ei32, int nwords) {
    __shared__ int red[8];
    int tid = threadIdx.x;
    int v = 0;
    for (int i = tid; i < 4096; i += 256) {
        int idx = 2 * i + 1;
        if (idx < nwords) v |= ei32[idx];
    }
#pragma unroll
    for (int m = 16; m >= 1; m >>= 1) v |= __shfl_xor_sync(FULLMASK, v, m);
    if ((tid & 31) == 0) red[tid >> 5] = v;
    __syncthreads();
    if (tid == 0) {
        int a = 0;
#pragma unroll
        for (int i = 0; i < 8; i++) a |= red[i];
        d_is64 = (a == 0) ? 1 : 0;
    }
}

__device__ __forceinline__ int load_edge(const void* eiv, size_t idx) {
    if (d_is64) return (int)((const long long*)eiv)[idx];
    return ((const int*)eiv)[idx];
}

// ---------------- CSR build --------------------------------------------------
__global__ void zero_deg_kernel(int n) {
    int i = blockIdx.x * blockDim.x + threadIdx.x;
    if (i < n) d_deg[i] = 0;
}

__global__ void count_deg_kernel(const void* __restrict__ eiv, int E, int N) {
    int i = blockIdx.x * blockDim.x + threadIdx.x;
    if (i < E) {
        int dst = load_edge(eiv, (size_t)E + i);
        if ((unsigned)dst < (unsigned)N) atomicAdd(&d_deg[dst], 1);
    }
}

// ---- parallel 3-pass exclusive scan of d_deg -> d_off (+ d_cur copy) --------
// pass 1: per-block local exclusive scan into d_off, block totals -> d_part
__global__ void scan_local_kernel(int n) {
    __shared__ int wsum[32];
    int tid = threadIdx.x, lane = tid & 31, wid = tid >> 5;
    int idx = blockIdx.x * 1024 + tid;
    int v = (idx < n) ? d_deg[idx] : 0;
    int incl = v;
#pragma unroll
    for (int off = 1; off < 32; off <<= 1) {
        int t = __shfl_up_sync(FULLMASK, incl, off);
        if (lane >= off) incl += t;
    }
    if (lane == 31) wsum[wid] = incl;
    __syncthreads();
    if (wid == 0) {
        int s = wsum[lane];
        int si = s;
#pragma unroll
        for (int off = 1; off < 32; off <<= 1) {
            int t = __shfl_up_sync(FULLMASK, si, off);
            if (lane >= off) si += t;
        }
        wsum[lane] = si - s;  // exclusive prefix of warp sums
    }
    __syncthreads();
    int excl = incl - v + wsum[wid];
    if (idx < n) d_off[idx] = excl;
    if (tid == 1023) d_part[blockIdx.x] = excl + v;  // block total
}

// pass 2: one small block scans the <=128 partials; writes total to d_off[n]
__global__ void scan_part_kernel(int nblk, int n) {
    __shared__ int sh[128];
    int tid = threadIdx.x;
    int v = (tid < nblk) ? d_part[tid] : 0;
    sh[tid] = v;
    __syncthreads();
#pragma unroll
    for (int off = 1; off < 128; off <<= 1) {
        int t = (tid >= off) ? sh[tid - off] : 0;
        __syncthreads();
        sh[tid] += t;
        __syncthreads();
    }
    int incl = sh[tid];
    if (tid < nblk) d_partscan[tid] = incl - v;
    if (tid == nblk - 1) d_off[n] = incl;  // grand total
}

// pass 3: add block offsets; materialize d_cur cursor copy
__global__ void scan_add_kernel(int n) {
    int idx = blockIdx.x * 1024 + threadIdx.x;
    if (idx < n) {
        int o = d_off[idx] + d_partscan[blockIdx.x];
        d_off[idx] = o;
        d_cur[idx] = o;
    }
}

__global__ void fill_csr_kernel(const void* __restrict__ eiv, int E, int N) {
    int i = blockIdx.x * blockDim.x + threadIdx.x;
    if (i < E) {
        int src = load_edge(eiv, (size_t)i);
        int dst = load_edge(eiv, (size_t)E + i);
        if ((unsigned)dst < (unsigned)N) {
            if ((unsigned)src >= (unsigned)N) src = 0;  // safety clamp
            int p = atomicAdd(&d_cur[dst], 1);
            if ((unsigned)p < (unsigned)NE) d_csr[p] = src;
        }
    }
}

// ---------------- SGEMM: C[N,128] = A[N,K](lda) @ W[K,128], f32x2 FMA --------
// gridDim.z selects (W, C): z=0 -> (W0, cdst0), z=1 -> (W1, cdst1).
// Aext == nullptr -> A = d_bufH. cdst: 0 = bufY, 1 = bufZ, 2 = bufF.
__global__ __launch_bounds__(256) void sgemm128_kernel(
    const float* __restrict__ Aext, int lda, int K,
    const float* __restrict__ W0, const float* __restrict__ W1,
    int cdst0, int cdst1, int N) {
    __shared__ __align__(16) float As[16 * 132];  // [k][row], padded stride
    __shared__ __align__(16) float Bs[16 * 128];  // [k][col]
    const float* A = Aext ? Aext : (const float*)d_bufH;
    const float* W = (blockIdx.z == 0) ? W0 : W1;
    int cdst = (blockIdx.z == 0) ? cdst0 : cdst1;
    float* C = (cdst == 0) ? (float*)d_bufY : (cdst == 1) ? (float*)d_bufZ
                                                          : (float*)d_bufF;
    int n0 = blockIdx.x * 128;
    int tid = threadIdx.x;
    int tr = (tid >> 4) * 8;  // row offset of 8x8 microtile
    int tc = (tid & 15) * 8;  // col offset
    unsigned long long acc[8][4];
#pragma unroll
    for (int i = 0; i < 8; i++)
#pragma unroll
        for (int j = 0; j < 4; j++) acc[i][j] = 0ull;

    for (int k0 = 0; k0 < K; k0 += 16) {
        __syncthreads();
        // stage A tile (128 rows x 16 k) transposed into As[k][row]
#pragma unroll
        for (int it = 0; it < 2; it++) {
            int s = tid + it * 256;
            int row = s >> 2;
            int kq = (s & 3) * 4;
            float4 v = make_float4(0.f, 0.f, 0.f, 0.f);
            int gr = n0 + row;
            if (gr < N) v = *(const float4*)(A + (size_t)gr * lda + k0 + kq);
            As[(kq + 0) * 132 + row] = v.x;
            As[(kq + 1) * 132 + row] = v.y;
            As[(kq + 2) * 132 + row] = v.z;
            As[(kq + 3) * 132 + row] = v.w;
        }
        // stage W tile (16 k x 128 cols)
#pragma unroll
        for (int it = 0; it < 2; it++) {
            int s = tid + it * 256;
            int kr = s >> 5;
            int c4 = (s & 31) * 4;
            *(float4*)(Bs + kr * 128 + c4) =
                *(const float4*)(W + (size_t)(k0 + kr) * 128 + c4);
        }
        __syncthreads();
#pragma unroll
        for (int k = 0; k < 16; k++) {
            float4 a0 = *(const float4*)(As + k * 132 + tr);
            float4 a1 = *(const float4*)(As + k * 132 + tr + 4);
            ulonglong2 b0 = *(const ulonglong2*)(Bs + k * 128 + tc);
            ulonglong2 b1v = *(const ulonglong2*)(Bs + k * 128 + tc + 4);
            float av[8] = {a0.x, a0.y, a0.z, a0.w, a1.x, a1.y, a1.z, a1.w};
            unsigned long long bv[4] = {b0.x, b0.y, b1v.x, b1v.y};
#pragma unroll
            for (int i = 0; i < 8; i++) {
                unsigned long long ad;
                unsigned int ai = __float_as_uint(av[i]);
                asm("mov.b64 %0, {%1, %1};" : "=l"(ad) : "r"(ai));
#pragma unroll
                for (int j = 0; j < 4; j++)
                    asm("fma.rn.f32x2 %0, %1, %2, %0;"
                        : "+l"(acc[i][j]) : "l"(ad), "l"(bv[j]));
            }
        }
    }
#pragma unroll
    for (int i = 0; i < 8; i++) {
        int gr = n0 + tr + i;
        if (gr < N) {
            float2 p0 = *(float2*)&acc[i][0];
            float2 p1 = *(float2*)&acc[i][1];
            float2 p2 = *(float2*)&acc[i][2];
            float2 p3 = *(float2*)&acc[i][3];
            *(float4*)(C + (size_t)gr * 128 + tc)     = make_float4(p0.x, p0.y, p1.x, p1.y);
            *(float4*)(C + (size_t)gr * 128 + tc + 4) = make_float4(p2.x, p2.y, p3.x, p3.y);
        }
    }
}

// ---------------- aggregate(mean) + bias + self + LayerNorm + ReLU -----------
// reads d_bufY (neighbor feats) + d_bufZ (self feats), writes d_bufH + coloff
__global__ void agg_ln_kernel(const float* __restrict__ bn, const float* __restrict__ g,
                              const float* __restrict__ be, int coloff, int N) {
    const float* y = (const float*)d_bufY;
    const float* z = (const float*)d_bufZ;
    float* hout = (float*)d_bufH + coloff;
    int w = (blockIdx.x * blockDim.x + threadIdx.x) >> 5;
    int lane = threadIdx.x & 31;
    if (w >= N) return;
    int s = d_off[w], e = d_off[w + 1];
    float4 acc = make_float4(0.f, 0.f, 0.f, 0.f);
    int i = s;
    // unroll-4: four independent 512B row-gathers in flight (MLP vs L2 latency)
    for (; i + 4 <= e; i += 4) {
        int s0 = d_csr[i], s1 = d_csr[i + 1], s2 = d_csr[i + 2], s3 = d_csr[i + 3];
        float4 v0 = *(const float4*)(y + (size_t)s0 * 128 + lane * 4);
        float4 v1 = *(const float4*)(y + (size_t)s1 * 128 + lane * 4);
        float4 v2 = *(const float4*)(y + (size_t)s2 * 128 + lane * 4);
        float4 v3 = *(const float4*)(y + (size_t)s3 * 128 + lane * 4);
        acc.x += (v0.x + v1.x) + (v2.x + v3.x);
        acc.y += (v0.y + v1.y) + (v2.y + v3.y);
        acc.z += (v0.z + v1.z) + (v2.z + v3.z);
        acc.w += (v0.w + v1.w) + (v2.w + v3.w);
    }
    for (; i < e; i++) {
        int s0 = d_csr[i];
        float4 v0 = *(const float4*)(y + (size_t)s0 * 128 + lane * 4);
        acc.x += v0.x; acc.y += v0.y; acc.z += v0.z; acc.w += v0.w;
    }
    int deg = e - s;
    float inv = 1.f / (float)(deg > 0 ? deg : 1);
    float4 zb = *(const float4*)(z + (size_t)w * 128 + lane * 4);
    float4 bn4 = *(const float4*)(bn + lane * 4);
    float4 t;
    t.x = fmaf(acc.x, inv, bn4.x + zb.x);
    t.y = fmaf(acc.y, inv, bn4.y + zb.y);
    t.z = fmaf(acc.z, inv, bn4.z + zb.z);
    t.w = fmaf(acc.w, inv, bn4.w + zb.w);
    float sum = t.x + t.y + t.z + t.w;
#pragma unroll
    for (int m = 16; m >= 1; m >>= 1) sum += __shfl_xor_sync(FULLMASK, sum, m);
    float mu = sum * (1.f / 128.f);
    float dx = t.x - mu, dy = t.y - mu, dz = t.z - mu, dw = t.w - mu;
    float sq = dx * dx + dy * dy + dz * dz + dw * dw;
#pragma unroll
    for (int m = 16; m >= 1; m >>= 1) sq += __shfl_xor_sync(FULLMASK, sq, m);
    float r = rsqrtf(sq * (1.f / 128.f) + 1e-5f);
    float4 g4 = *(const float4*)(g + lane * 4);
    float4 be4 = *(const float4*)(be + lane * 4);
    float4 h;
    h.x = fmaxf(fmaf(dx * r, g4.x, be4.x), 0.f);
    h.y = fmaxf(fmaf(dy * r, g4.y, be4.y), 0.f);
    h.z = fmaxf(fmaf(dz * r, g4.z, be4.z), 0.f);
    h.w = fmaxf(fmaf(dw * r, g4.w, be4.w), 0.f);
    *(float4*)(hout + (size_t)w * 256 + lane * 4) = h;
}

// ---------------- MLP head: out = relu((F+bjk)@W1+b1)@W2+b2 ------------------
__global__ __launch_bounds__(256) void head_kernel(
    const float* __restrict__ bjk,
    const float* __restrict__ W1, const float* __restrict__ b1,
    const float* __restrict__ W2, const float* __restrict__ b2,
    float* __restrict__ out, int N) {
    __shared__ __align__(16) float W1T[32 * 132];  // [j][k], padded stride
    __shared__ __align__(16) float W2s[32 * 16];
    __shared__ __align__(16) float b1s[32];
    __shared__ __align__(16) float b2s[16];
    __shared__ __align__(16) float bjs[128];
    const float* F = (const float*)d_bufF;
    int tid = threadIdx.x;
    for (int s = tid; s < 128 * 32; s += 256) {
        int k = s >> 5, j = s & 31;
        W1T[j * 132 + k] = W1[s];
    }
    for (int s = tid; s < 512; s += 256) W2s[s] = W2[s];
    if (tid < 32) b1s[tid] = b1[tid];
    if (tid < 16) b2s[tid] = b2[tid];
    if (tid < 128) bjs[tid] = bjk[tid];
    __syncthreads();
    int lane = tid & 31;
    int wg = (blockIdx.x * 256 + tid) >> 5;
    int nw = (gridDim.x * 256) >> 5;
    for (int node = wg; node < N; node += nw) {
        float4 f = *(const float4*)(F + (size_t)node * 128 + lane * 4);
        float4 bj = *(const float4*)(bjs + lane * 4);
        f.x += bj.x; f.y += bj.y; f.z += bj.z; f.w += bj.w;
        float p[32];
#pragma unroll
        for (int j = 0; j < 32; j++) {
            float4 wv = *(const float4*)(W1T + j * 132 + lane * 4);
            p[j] = f.x * wv.x + f.y * wv.y + f.z * wv.z + f.w * wv.w;
        }
#pragma unroll
        for (int m = 16; m >= 1; m >>= 1) {
#pragma unroll
            for (int j = 0; j < 32; j++) p[j] += __shfl_xor_sync(FULLMASK, p[j], m);
        }
        if (lane < 16) {
            float o = b2s[lane];
#pragma unroll
            for (int j = 0; j < 32; j++) {
                float hj = fmaxf(p[j] + b1s[j], 0.f);
                o = fmaf(hj, W2s[j * 16 + lane], o);
            }
            out[(size_t)node * 16 + lane] = o;
        }
    }
}

// ---------------- launch: kernel launches ONLY (graph-capturable) ------------
extern "C" void kernel_launch(void* const* d_in, const int* in_sizes, int n_in,
                              void* d_out, int out_size) {
    const float* x     = (const float*)d_in[0];
    const void*  eiv   = d_in[1];  // int32 or int64 edge_index, detected on-device
    const float* W_nl0 = (const float*)d_in[2];
    const float* b_nl0 = (const float*)d_in[3];
    const float* W_r0  = (const float*)d_in[4];
    const float* W_nl1 = (const float*)d_in[5];
    const float* b_nl1 = (const float*)d_in[6];
    const float* W_r1  = (const float*)d_in[7];
    const float* g0    = (const float*)d_in[8];
    const float* be0   = (const float*)d_in[9];
    const float* g1    = (const float*)d_in[10];
    const float* be1   = (const float*)d_in[11];
    const float* W_jk  = (const float*)d_in[12];
    const float* b_jk  = (const float*)d_in[13];
    const float* W_h1  = (const float*)d_in[14];
    const float* b_h1  = (const float*)d_in[15];
    const float* W_h2  = (const float*)d_in[16];
    const float* b_h2  = (const float*)d_in[17];
    float* out = (float*)d_out;

    int N = in_sizes[0] / 256;
    int E = in_sizes[1] / 2;
    if (N > NN) N = NN;
    if (E > NE) E = NE;

    int gN = (N + 255) / 256;
    int gE = (E + 255) / 256;
    int gGemm = (N + 127) / 128;
    int gAgg = (N + 7) / 8;       // 8 warps per 256-thread block
    int gScan = (N + 1023) / 1024;

    dim3 gPair(gGemm, 1, 2);

    // Launch order puts the layer-0 dual GEMM at launch #6 so the ncu capture
    // (-s 5 -c 1) profiles the GEMM next round instead of a CSR helper.
    detect_dtype_kernel<<<1, 256>>>((const int*)eiv, in_sizes[1]);        // 1
    zero_deg_kernel<<<gN, 256>>>(N);                                      // 2
    count_deg_kernel<<<gE, 256>>>(eiv, E, N);                             // 3
    scan_local_kernel<<<gScan, 1024>>>(N);                                // 4
    scan_part_kernel<<<1, 128>>>(gScan, N);                               // 5
    // layer 0 dual GEMM: bufY = x@W_nl0, bufZ = x@W_r0 (independent of CSR)
    sgemm128_kernel<<<gPair, 256>>>(x, 256, 256, W_nl0, W_r0, 0, 1, N);   // 6 (profiled)
    scan_add_kernel<<<gScan, 1024>>>(N);                                  // 7
    fill_csr_kernel<<<gE, 256>>>(eiv, E, N);                              // 8

    // layer 0 epilogue: agg+LN+ReLU -> h0 (bufH cols 0..127)
    agg_ln_kernel<<<gAgg, 256>>>(b_nl0, g0, be0, 0, N);

    // layer 1 dual GEMM + epilogue -> h1 (bufH cols 128..255)
    sgemm128_kernel<<<gPair, 256>>>(nullptr, 256, 128, W_nl1, W_r1, 0, 1, N);
    agg_ln_kernel<<<gAgg, 256>>>(b_nl1, g1, be1, 128, N);

    // JK projection: bufF = [h0|h1] @ W_jk (bias folded into head kernel)
    sgemm128_kernel<<<dim3(gGemm, 1, 1), 256>>>(nullptr, 256, 256, W_jk, W_jk, 2, 2, N);

    // MLP head
    head_kernel<<<592, 256>>>(b_jk, W_h1, b_h1, W_h2, b_h2, out, N);
}

// round 12
// speedup vs baseline: 1.2948x; 1.1512x over previous
#include <cuda_runtime.h>

#define NN 100000
#define NE 1600000
#define FULLMASK 0xffffffffu

// ---------------- static device scratch (no allocations allowed) -------------
static __device__ __align__(256) float d_bufH[(size_t)NN * 256]; // h0 | h1 (JK concat)
static __device__ __align__(256) float d_bufY[(size_t)NN * 128]; // neighbor-transform
static __device__ __align__(256) float d_bufZ[(size_t)NN * 128]; // self-transform
static __device__ __align__(256) float d_bufT[(size_t)NN * 32];  // head hidden (relu)
static __device__ __align__(256) float d_Wc[256 * 32];           // W_jk @ W_h1
static __device__ __align__(256) float d_bc[32];                 // b_jk@W_h1 + b_h1
static __device__ int d_deg[NN];
static __device__ int d_off[NN + 1];
static __device__ int d_cur[NN];
static __device__ int d_csr[NE];
static __device__ int d_part[128];      // per-block scan partials
static __device__ int d_partscan[128];  // exclusive-scanned partials
static __device__ int d_is64;           // 1 if edge_index is int64, 0 if int32

// ---------------- edge dtype detection ---------------------------------------
__global__ void detect_dtype_kernel(const int* __restrict__ ei32, int nwords) {
    __shared__ int red[8];
    int tid = threadIdx.x;
    int v = 0;
    for (int i = tid; i < 4096; i += 256) {
        int idx = 2 * i + 1;
        if (idx < nwords) v |= ei32[idx];
    }
#pragma unroll
    for (int m = 16; m >= 1; m >>= 1) v |= __shfl_xor_sync(FULLMASK, v, m);
    if ((tid & 31) == 0) red[tid >> 5] = v;
    __syncthreads();
    if (tid == 0) {
        int a = 0;
#pragma unroll
        for (int i = 0; i < 8; i++) a |= red[i];
        d_is64 = (a == 0) ? 1 : 0;
    }
}

__device__ __forceinline__ int load_edge(const void* eiv, size_t idx) {
    if (d_is64) return (int)((const long long*)eiv)[idx];
    return ((const int*)eiv)[idx];
}

// ---------------- CSR build --------------------------------------------------
__global__ void zero_deg_kernel(int n) {
    int i = blockIdx.x * blockDim.x + threadIdx.x;
    if (i < n) d_deg[i] = 0;
}

__global__ void count_deg_kernel(const void* __restrict__ eiv, int E, int N) {
    int i = blockIdx.x * blockDim.x + threadIdx.x;
    if (i < E) {
        int dst = load_edge(eiv, (size_t)E + i);
        if ((unsigned)dst < (unsigned)N) atomicAdd(&d_deg[dst], 1);
    }
}

__global__ void scan_local_kernel(int n) {
    __shared__ int wsum[32];
    int tid = threadIdx.x, lane = tid & 31, wid = tid >> 5;
    int idx = blockIdx.x * 1024 + tid;
    int v = (idx < n) ? d_deg[idx] : 0;
    int incl = v;
#pragma unroll
    for (int off = 1; off < 32; off <<= 1) {
        int t = __shfl_up_sync(FULLMASK, incl, off);
        if (lane >= off) incl += t;
    }
    if (lane == 31) wsum[wid] = incl;
    __syncthreads();
    if (wid == 0) {
        int s = wsum[lane];
        int si = s;
#pragma unroll
        for (int off = 1; off < 32; off <<= 1) {
            int t = __shfl_up_sync(FULLMASK, si, off);
            if (lane >= off) si += t;
        }
        wsum[lane] = si - s;
    }
    __syncthreads();
    int excl = incl - v + wsum[wid];
    if (idx < n) d_off[idx] = excl;
    if (tid == 1023) d_part[blockIdx.x] = excl + v;
}

__global__ void scan_part_kernel(int nblk, int n) {
    __shared__ int sh[128];
    int tid = threadIdx.x;
    int v = (tid < nblk) ? d_part[tid] : 0;
    sh[tid] = v;
    __syncthreads();
#pragma unroll
    for (int off = 1; off < 128; off <<= 1) {
        int t = (tid >= off) ? sh[tid - off] : 0;
        __syncthreads();
        sh[tid] += t;
        __syncthreads();
    }
    int incl = sh[tid];
    if (tid < nblk) d_partscan[tid] = incl - v;
    if (tid == nblk - 1) d_off[n] = incl;
}

__global__ void scan_add_kernel(int n) {
    int idx = blockIdx.x * 1024 + threadIdx.x;
    if (idx < n) {
        int o = d_off[idx] + d_partscan[blockIdx.x];
        d_off[idx] = o;
        d_cur[idx] = o;
    }
}

__global__ void fill_csr_kernel(const void* __restrict__ eiv, int E, int N) {
    int i = blockIdx.x * blockDim.x + threadIdx.x;
    if (i < E) {
        int src = load_edge(eiv, (size_t)i);
        int dst = load_edge(eiv, (size_t)E + i);
        if ((unsigned)dst < (unsigned)N) {
            if ((unsigned)src >= (unsigned)N) src = 0;
            int p = atomicAdd(&d_cur[dst], 1);
            if ((unsigned)p < (unsigned)NE) d_csr[p] = src;
        }
    }
}

// ---------------- weight folding: Wc = W_jk @ W_h1, bc = b_jk@W_h1 + b_h1 ----
__global__ void fold_w_kernel(const float* __restrict__ Wjk,
                              const float* __restrict__ W1h,
                              const float* __restrict__ bjk,
                              const float* __restrict__ b1) {
    int t = blockIdx.x * 256 + threadIdx.x;
    if (t < 8192) {
        int k = t >> 5, c = t & 31;
        float s = 0.f;
        for (int j = 0; j < 128; j++)
            s = fmaf(Wjk[k * 128 + j], W1h[j * 32 + c], s);
        d_Wc[k * 32 + c] = s;
    }
    if (t < 32) {
        float s = b1[t];
        for (int j = 0; j < 128; j++) s = fmaf(bjk[j], W1h[j * 32 + t], s);
        d_bc[t] = s;
    }
}

// ---------------- SGEMM: C[N,128] = A[N,K](lda) @ W[K,128] -------------------
// 256-row x 128-col block tile, 16x8 microtile, f32x2 packed FMA.
// Per k-step: 96B smem / 128 MACs per thread -> compute-bound (192 < 256 cyc).
// gridDim.z selects (W, C). Aext == nullptr -> A = d_bufH.
__global__ __launch_bounds__(256) void sgemm256_kernel(
    const float* __restrict__ Aext, int lda, int K,
    const float* __restrict__ W0, const float* __restrict__ W1,
    int cdst0, int cdst1, int N) {
    __shared__ __align__(16) float As[16 * 260];  // [k][row 0..255], pad 4
    __shared__ __align__(16) float Bs[16 * 128];  // [k][col]
    const float* A = Aext ? Aext : (const float*)d_bufH;
    const float* W = (blockIdx.z == 0) ? W0 : W1;
    int cdst = (blockIdx.z == 0) ? cdst0 : cdst1;
    float* C = (cdst == 0) ? (float*)d_bufY : (float*)d_bufZ;
    int n0 = blockIdx.x * 256;
    int tid = threadIdx.x;
    int tr = (tid >> 4) * 16;  // 16 row-groups x 16 rows
    int tc = (tid & 15) * 8;   // 16 col-groups x 8 cols
    unsigned long long acc[16][4];
#pragma unroll
    for (int i = 0; i < 16; i++)
#pragma unroll
        for (int j = 0; j < 4; j++) acc[i][j] = 0ull;

    for (int k0 = 0; k0 < K; k0 += 16) {
        __syncthreads();
        // stage A tile (256 rows x 16 k) transposed into As[k][row]
#pragma unroll
        for (int it = 0; it < 4; it++) {
            int s = tid + it * 256;
            int row = s >> 2;
            int kq = (s & 3) * 4;
            float4 v = make_float4(0.f, 0.f, 0.f, 0.f);
            int gr = n0 + row;
            if (gr < N) v = *(const float4*)(A + (size_t)gr * lda + k0 + kq);
            As[(kq + 0) * 260 + row] = v.x;
            As[(kq + 1) * 260 + row] = v.y;
            As[(kq + 2) * 260 + row] = v.z;
            As[(kq + 3) * 260 + row] = v.w;
        }
        // stage W tile (16 k x 128 cols)
#pragma unroll
        for (int it = 0; it < 2; it++) {
            int s = tid + it * 256;
            int kr = s >> 5;
            int c4 = (s & 31) * 4;
            *(float4*)(Bs + kr * 128 + c4) =
                *(const float4*)(W + (size_t)(k0 + kr) * 128 + c4);
        }
        __syncthreads();
#pragma unroll
        for (int k = 0; k < 16; k++) {
            float4 a0 = *(const float4*)(As + k * 260 + tr);
            float4 a1 = *(const float4*)(As + k * 260 + tr + 4);
            float4 a2 = *(const float4*)(As + k * 260 + tr + 8);
            float4 a3 = *(const float4*)(As + k * 260 + tr + 12);
            ulonglong2 b0 = *(const ulonglong2*)(Bs + k * 128 + tc);
            ulonglong2 b1v = *(const ulonglong2*)(Bs + k * 128 + tc + 4);
            float av[16] = {a0.x, a0.y, a0.z, a0.w, a1.x, a1.y, a1.z, a1.w,
                            a2.x, a2.y, a2.z, a2.w, a3.x, a3.y, a3.z, a3.w};
            unsigned long long bv[4] = {b0.x, b0.y, b1v.x, b1v.y};
#pragma unroll
            for (int i = 0; i < 16; i++) {
                unsigned long long ad;
                unsigned int ai = __float_as_uint(av[i]);
                asm("mov.b64 %0, {%1, %1};" : "=l"(ad) : "r"(ai));
#pragma unroll
                for (int j = 0; j < 4; j++)
                    asm("fma.rn.f32x2 %0, %1, %2, %0;"
                        : "+l"(acc[i][j]) : "l"(ad), "l"(bv[j]));
            }
        }
    }
#pragma unroll
    for (int i = 0; i < 16; i++) {
        int gr = n0 + tr + i;
        if (gr < N) {
            float2 p0 = *(float2*)&acc[i][0];
            float2 p1 = *(float2*)&acc[i][1];
            float2 p2 = *(float2*)&acc[i][2];
            float2 p3 = *(float2*)&acc[i][3];
            *(float4*)(C + (size_t)gr * 128 + tc)     = make_float4(p0.x, p0.y, p1.x, p1.y);
            *(float4*)(C + (size_t)gr * 128 + tc + 4) = make_float4(p2.x, p2.y, p3.x, p3.y);
        }
    }
}

// ---------------- aggregate(mean) + bias + self + LayerNorm + ReLU -----------
__global__ void agg_ln_kernel(const float* __restrict__ bn, const float* __restrict__ g,
                              const float* __restrict__ be, int coloff, int N) {
    const float* y = (const float*)d_bufY;
    const float* z = (const float*)d_bufZ;
    float* hout = (float*)d_bufH + coloff;
    int w = (blockIdx.x * blockDim.x + threadIdx.x) >> 5;
    int lane = threadIdx.x & 31;
    if (w >= N) return;
    int s = d_off[w], e = d_off[w + 1];
    float4 acc = make_float4(0.f, 0.f, 0.f, 0.f);
    int i = s;
    for (; i + 4 <= e; i += 4) {
        int s0 = d_csr[i], s1 = d_csr[i + 1], s2 = d_csr[i + 2], s3 = d_csr[i + 3];
        float4 v0 = *(const float4*)(y + (size_t)s0 * 128 + lane * 4);
        float4 v1 = *(const float4*)(y + (size_t)s1 * 128 + lane * 4);
        float4 v2 = *(const float4*)(y + (size_t)s2 * 128 + lane * 4);
        float4 v3 = *(const float4*)(y + (size_t)s3 * 128 + lane * 4);
        acc.x += (v0.x + v1.x) + (v2.x + v3.x);
        acc.y += (v0.y + v1.y) + (v2.y + v3.y);
        acc.z += (v0.z + v1.z) + (v2.z + v3.z);
        acc.w += (v0.w + v1.w) + (v2.w + v3.w);
    }
    for (; i < e; i++) {
        int s0 = d_csr[i];
        float4 v0 = *(const float4*)(y + (size_t)s0 * 128 + lane * 4);
        acc.x += v0.x; acc.y += v0.y; acc.z += v0.z; acc.w += v0.w;
    }
    int deg = e - s;
    float inv = 1.f / (float)(deg > 0 ? deg : 1);
    float4 zb = *(const float4*)(z + (size_t)w * 128 + lane * 4);
    float4 bn4 = *(const float4*)(bn + lane * 4);
    float4 t;
    t.x = fmaf(acc.x, inv, bn4.x + zb.x);
    t.y = fmaf(acc.y, inv, bn4.y + zb.y);
    t.z = fmaf(acc.z, inv, bn4.z + zb.z);
    t.w = fmaf(acc.w, inv, bn4.w + zb.w);
    float sum = t.x + t.y + t.z + t.w;
#pragma unroll
    for (int m = 16; m >= 1; m >>= 1) sum += __shfl_xor_sync(FULLMASK, sum, m);
    float mu = sum * (1.f / 128.f);
    float dx = t.x - mu, dy = t.y - mu, dz = t.z - mu, dw = t.w - mu;
    float sq = dx * dx + dy * dy + dz * dz + dw * dw;
#pragma unroll
    for (int m = 16; m >= 1; m >>= 1) sq += __shfl_xor_sync(FULLMASK, sq, m);
    float r = rsqrtf(sq * (1.f / 128.f) + 1e-5f);
    float4 g4 = *(const float4*)(g + lane * 4);
    float4 be4 = *(const float4*)(be + lane * 4);
    float4 h;
    h.x = fmaxf(fmaf(dx * r, g4.x, be4.x), 0.f);
    h.y = fmaxf(fmaf(dy * r, g4.y, be4.y), 0.f);
    h.z = fmaxf(fmaf(dz * r, g4.z, be4.z), 0.f);
    h.w = fmaxf(fmaf(dw * r, g4.w, be4.w), 0.f);
    *(float4*)(hout + (size_t)w * 256 + lane * 4) = h;
}

// ---------------- head stage A: T = relu(H[N,256] @ Wc[256,32] + bc) ---------
// 256-row x 32-col tile, 8x4 microtile, 256 threads.
__global__ __launch_bounds__(256) void head_gemm_kernel(int N) {
    __shared__ __align__(16) float As[16 * 260];
    __shared__ __align__(16) float Bs[16 * 32];
    const float* A = (const float*)d_bufH;
    float* T = (float*)d_bufT;
    int n0 = blockIdx.x * 256;
    int tid = threadIdx.x;
    int tr = (tid >> 3) * 8;  // 32 row-groups x 8 rows
    int tc = (tid & 7) * 4;   // 8 col-groups x 4 cols
    unsigned long long acc[8][2];
#pragma unroll
    for (int i = 0; i < 8; i++) { acc[i][0] = 0ull; acc[i][1] = 0ull; }

    for (int k0 = 0; k0 < 256; k0 += 16) {
        __syncthreads();
#pragma unroll
        for (int it = 0; it < 4; it++) {
            int s = tid + it * 256;
            int row = s >> 2;
            int kq = (s & 3) * 4;
            float4 v = make_float4(0.f, 0.f, 0.f, 0.f);
            int gr = n0 + row;
            if (gr < N) v = *(const float4*)(A + (size_t)gr * 256 + k0 + kq);
            As[(kq + 0) * 260 + row] = v.x;
            As[(kq + 1) * 260 + row] = v.y;
            As[(kq + 2) * 260 + row] = v.z;
            As[(kq + 3) * 260 + row] = v.w;
        }
        if (tid < 128) {
            int kr = tid >> 3;
            int c4 = (tid & 7) * 4;
            *(float4*)(Bs + kr * 32 + c4) =
                *(const float4*)((const float*)d_Wc + (k0 + kr) * 32 + c4);
        }
        __syncthreads();
#pragma unroll
        for (int k = 0; k < 16; k++) {
            float4 a0 = *(const float4*)(As + k * 260 + tr);
            float4 a1 = *(const float4*)(As + k * 260 + tr + 4);
            ulonglong2 b0 = *(const ulonglong2*)(Bs + k * 32 + tc);
            float av[8] = {a0.x, a0.y, a0.z, a0.w, a1.x, a1.y, a1.z, a1.w};
#pragma unroll
            for (int i = 0; i < 8; i++) {
                unsigned long long ad;
                unsigned int ai = __float_as_uint(av[i]);
                asm("mov.b64 %0, {%1, %1};" : "=l"(ad) : "r"(ai));
                asm("fma.rn.f32x2 %0, %1, %2, %0;" : "+l"(acc[i][0]) : "l"(ad), "l"(b0.x));
                asm("fma.rn.f32x2 %0, %1, %2, %0;" : "+l"(acc[i][1]) : "l"(ad), "l"(b0.y));
            }
        }
    }
    float4 bcv = *(const float4*)((const float*)d_bc + tc);
#pragma unroll
    for (int i = 0; i < 8; i++) {
        int gr = n0 + tr + i;
        if (gr < N) {
            float2 p0 = *(float2*)&acc[i][0];
            float2 p1 = *(float2*)&acc[i][1];
            float4 o;
            o.x = fmaxf(p0.x + bcv.x, 0.f);
            o.y = fmaxf(p0.y + bcv.y, 0.f);
            o.z = fmaxf(p1.x + bcv.z, 0.f);
            o.w = fmaxf(p1.y + bcv.w, 0.f);
            *(float4*)(T + (size_t)gr * 32 + tc) = o;
        }
    }
}

// ---------------- head stage B: out = T @ W2 + b2 ----------------------------
// warp per node; lane j holds W2 row j in registers; 31-shuffle transpose-reduce.
__global__ void head_out_kernel(const float* __restrict__ W2,
                                const float* __restrict__ b2,
                                float* __restrict__ out, int N) {
    int lane = threadIdx.x & 31;
    float w2r[16];
#pragma unroll
    for (int c4 = 0; c4 < 16; c4 += 4) {
        float4 w = *(const float4*)(W2 + lane * 16 + c4);
        w2r[c4] = w.x; w2r[c4 + 1] = w.y; w2r[c4 + 2] = w.z; w2r[c4 + 3] = w.w;
    }
    float bv = (lane < 16) ? b2[lane] : 0.f;
    int wg = (blockIdx.x * blockDim.x + threadIdx.x) >> 5;
    int nw = (gridDim.x * blockDim.x) >> 5;
    const float* T = (const float*)d_bufT;
    for (int node = wg; node < N; node += nw) {
        float h = T[(size_t)node * 32 + lane];
        float v[16];
#pragma unroll
        for (int c = 0; c < 16; c++) v[c] = h * w2r[c];
        // fold upper 16 lanes onto lower
#pragma unroll
        for (int c = 0; c < 16; c++) v[c] += __shfl_xor_sync(FULLMASK, v[c], 16);
        // transpose-reduce: lane l (0..15) ends with total for output l
#pragma unroll
        for (int s = 8; s >= 1; s >>= 1) {
            int up = lane & s;
#pragma unroll
            for (int k = 0; k < 8; k++) {
                if (k < s) {
                    float x = up ? v[k] : v[k + s];
                    x = __shfl_xor_sync(FULLMASK, x, s);
                    v[k] = (up ? v[k + s] : v[k]) + x;
                }
            }
        }
        if (lane < 16) out[(size_t)node * 16 + lane] = v[0] + bv;
    }
}

// ---------------- launch: kernel launches ONLY (graph-capturable) ------------
extern "C" void kernel_launch(void* const* d_in, const int* in_sizes, int n_in,
                              void* d_out, int out_size) {
    const float* x     = (const float*)d_in[0];
    const void*  eiv   = d_in[1];  // int32 or int64 edge_index, detected on-device
    const float* W_nl0 = (const float*)d_in[2];
    const float* b_nl0 = (const float*)d_in[3];
    const float* W_r0  = (const float*)d_in[4];
    const float* W_nl1 = (const float*)d_in[5];
    const float* b_nl1 = (const float*)d_in[6];
    const float* W_r1  = (const float*)d_in[7];
    const float* g0    = (const float*)d_in[8];
    const float* be0   = (const float*)d_in[9];
    const float* g1    = (const float*)d_in[10];
    const float* be1   = (const float*)d_in[11];
    const float* W_jk  = (const float*)d_in[12];
    const float* b_jk  = (const float*)d_in[13];
    const float* W_h1  = (const float*)d_in[14];
    const float* b_h1  = (const float*)d_in[15];
    const float* W_h2  = (const float*)d_in[16];
    const float* b_h2  = (const float*)d_in[17];
    float* out = (float*)d_out;

    int N = in_sizes[0] / 256;
    int E = in_sizes[1] / 2;
    if (N > NN) N = NN;
    if (E > NE) E = NE;

    int gN = (N + 255) / 256;
    int gE = (E + 255) / 256;
    int gG = (N + 255) / 256;      // 256-row GEMM tiles
    int gAgg = (N + 7) / 8;
    int gScan = (N + 1023) / 1024;

    dim3 gPair(gG, 1, 2);

    // CSR build + weight folding
    detect_dtype_kernel<<<1, 256>>>((const int*)eiv, in_sizes[1]);
    zero_deg_kernel<<<gN, 256>>>(N);
    count_deg_kernel<<<gE, 256>>>(eiv, E, N);
    scan_local_kernel<<<gScan, 1024>>>(N);
    scan_part_kernel<<<1, 128>>>(gScan, N);
    // layer 0 dual GEMM early (independent of CSR); also launch slot 6 for ncu
    sgemm256_kernel<<<gPair, 256>>>(x, 256, 256, W_nl0, W_r0, 0, 1, N);
    scan_add_kernel<<<gScan, 1024>>>(N);
    fill_csr_kernel<<<gE, 256>>>(eiv, E, N);
    fold_w_kernel<<<32, 256>>>(W_jk, W_h1, b_jk, b_h1);

    // layer 0 epilogue -> h0 (bufH cols 0..127)
    agg_ln_kernel<<<gAgg, 256>>>(b_nl0, g0, be0, 0, N);

    // layer 1 dual GEMM + epilogue -> h1 (bufH cols 128..255)
    sgemm256_kernel<<<gPair, 256>>>(nullptr, 256, 128, W_nl1, W_r1, 0, 1, N);
    agg_ln_kernel<<<gAgg, 256>>>(b_nl1, g1, be1, 128, N);

    // head: T = relu(H @ (Wjk@W1) + bc); out = T @ W2 + b2
    head_gemm_kernel<<<gG, 256>>>(N);
    head_out_kernel<<<296, 256>>>(W_h2, b_h2, out, N);
}

// round 13
// speedup vs baseline: 1.3373x; 1.0328x over previous
#include <cuda_runtime.h>

#define NN 100000
#define NE 1600000
#define FULLMASK 0xffffffffu

// ---------------- static device scratch (no allocations allowed) -------------
static __device__ __align__(256) float d_bufH[(size_t)NN * 256]; // h0 | h1 (JK concat)
static __device__ __align__(256) float d_bufY[(size_t)NN * 128]; // neighbor-transform
static __device__ __align__(256) float d_bufZ[(size_t)NN * 128]; // self-transform
static __device__ __align__(256) float d_bufT[(size_t)NN * 32];  // head hidden (relu)
static __device__ __align__(256) float d_Wc[256 * 32];           // W_jk @ W_h1
static __device__ __align__(256) float d_bc[32];                 // b_jk@W_h1 + b_h1
static __device__ int d_deg[NN];
static __device__ int d_off[NN + 1];
static __device__ int d_cur[NN];
static __device__ int d_csr[NE];
static __device__ int d_part[128];
static __device__ int d_partscan[128];
static __device__ int d_is64;

// ---------------- edge dtype detection ---------------------------------------
__global__ void detect_dtype_kernel(const int* __restrict__ ei32, int nwords) {
    __shared__ int red[8];
    int tid = threadIdx.x;
    int v = 0;
    for (int i = tid; i < 4096; i += 256) {
        int idx = 2 * i + 1;
        if (idx < nwords) v |= ei32[idx];
    }
#pragma unroll
    for (int m = 16; m >= 1; m >>= 1) v |= __shfl_xor_sync(FULLMASK, v, m);
    if ((tid & 31) == 0) red[tid >> 5] = v;
    __syncthreads();
    if (tid == 0) {
        int a = 0;
#pragma unroll
        for (int i = 0; i < 8; i++) a |= red[i];
        d_is64 = (a == 0) ? 1 : 0;
    }
}

__device__ __forceinline__ int load_edge(const void* eiv, size_t idx) {
    if (d_is64) return (int)((const long long*)eiv)[idx];
    return ((const int*)eiv)[idx];
}

// ---------------- CSR build --------------------------------------------------
__global__ void zero_deg_kernel(int n) {
    int i = blockIdx.x * blockDim.x + threadIdx.x;
    if (i < n) d_deg[i] = 0;
}

__global__ void count_deg_kernel(const void* __restrict__ eiv, int E, int N) {
    int i = blockIdx.x * blockDim.x + threadIdx.x;
    if (i < E) {
        int dst = load_edge(eiv, (size_t)E + i);
        if ((unsigned)dst < (unsigned)N) atomicAdd(&d_deg[dst], 1);
    }
}

__global__ void scan_local_kernel(int n) {
    __shared__ int wsum[32];
    int tid = threadIdx.x, lane = tid & 31, wid = tid >> 5;
    int idx = blockIdx.x * 1024 + tid;
    int v = (idx < n) ? d_deg[idx] : 0;
    int incl = v;
#pragma unroll
    for (int off = 1; off < 32; off <<= 1) {
        int t = __shfl_up_sync(FULLMASK, incl, off);
        if (lane >= off) incl += t;
    }
    if (lane == 31) wsum[wid] = incl;
    __syncthreads();
    if (wid == 0) {
        int s = wsum[lane];
        int si = s;
#pragma unroll
        for (int off = 1; off < 32; off <<= 1) {
            int t = __shfl_up_sync(FULLMASK, si, off);
            if (lane >= off) si += t;
        }
        wsum[lane] = si - s;
    }
    __syncthreads();
    int excl = incl - v + wsum[wid];
    if (idx < n) d_off[idx] = excl;
    if (tid == 1023) d_part[blockIdx.x] = excl + v;
}

__global__ void scan_part_kernel(int nblk, int n) {
    __shared__ int sh[128];
    int tid = threadIdx.x;
    int v = (tid < nblk) ? d_part[tid] : 0;
    sh[tid] = v;
    __syncthreads();
#pragma unroll
    for (int off = 1; off < 128; off <<= 1) {
        int t = (tid >= off) ? sh[tid - off] : 0;
        __syncthreads();
        sh[tid] += t;
        __syncthreads();
    }
    int incl = sh[tid];
    if (tid < nblk) d_partscan[tid] = incl - v;
    if (tid == nblk - 1) d_off[n] = incl;
}

__global__ void scan_add_kernel(int n) {
    int idx = blockIdx.x * 1024 + threadIdx.x;
    if (idx < n) {
        int o = d_off[idx] + d_partscan[blockIdx.x];
        d_off[idx] = o;
        d_cur[idx] = o;
    }
}

__global__ void fill_csr_kernel(const void* __restrict__ eiv, int E, int N) {
    int i = blockIdx.x * blockDim.x + threadIdx.x;
    if (i < E) {
        int src = load_edge(eiv, (size_t)i);
        int dst = load_edge(eiv, (size_t)E + i);
        if ((unsigned)dst < (unsigned)N) {
            if ((unsigned)src >= (unsigned)N) src = 0;
            int p = atomicAdd(&d_cur[dst], 1);
            if ((unsigned)p < (unsigned)NE) d_csr[p] = src;
        }
    }
}

// ---------------- weight folding: Wc = W_jk @ W_h1, bc = b_jk@W_h1 + b_h1 ----
__global__ void fold_w_kernel(const float* __restrict__ Wjk,
                              const float* __restrict__ W1h,
                              const float* __restrict__ bjk,
                              const float* __restrict__ b1) {
    int t = blockIdx.x * 256 + threadIdx.x;
    if (t < 8192) {
        int k = t >> 5, c = t & 31;
        float s = 0.f;
        for (int j = 0; j < 128; j++)
            s = fmaf(Wjk[k * 128 + j], W1h[j * 32 + c], s);
        d_Wc[k * 32 + c] = s;
    }
    if (t < 32) {
        float s = b1[t];
        for (int j = 0; j < 128; j++) s = fmaf(bjk[j], W1h[j * 32 + t], s);
        d_bc[t] = s;
    }
}

// ---------------- SGEMM: C[N,128] = A[N,K](lda) @ W[K,128] -------------------
// 256x128 block tile, 16x8 microtile with ROW-PAIR f32x2 accumulators:
//   acc[ip][j] = (C[tr+2ip][tc+j], C[tr+2ip+1][tc+j])
// A pairs load directly as 64-bit from transposed As (no dup movs);
// only B needs per-k duplication (8 movs vs 16). Double-buffered smem with
// register prefetch hides global-load latency behind the FFMA2 stream.
// Smem: 2*(16*256*4) + 2*(16*128*4) = 49152 B (exactly the 48KB static cap).
__global__ __launch_bounds__(256) void sgemm256_kernel(
    const float* __restrict__ Aext, int lda, int K,
    const float* __restrict__ W0, const float* __restrict__ W1,
    int cdst0, int cdst1, int N) {
    __shared__ __align__(16) float As[2][16 * 256];  // [k][row]
    __shared__ __align__(16) float Bs[2][16 * 128];  // [k][col]
    const float* A = Aext ? Aext : (const float*)d_bufH;
    const float* W = (blockIdx.z == 0) ? W0 : W1;
    int cdst = (blockIdx.z == 0) ? cdst0 : cdst1;
    float* C = (cdst == 0) ? (float*)d_bufY : (float*)d_bufZ;
    int n0 = blockIdx.x * 256;
    int tid = threadIdx.x;
    int tr = (tid >> 4) * 16;  // 16 row-groups x 16 rows
    int tc = (tid & 15) * 8;   // 16 col-groups x 8 cols

    unsigned long long acc[8][8];  // [row-pair][col]
#pragma unroll
    for (int i = 0; i < 8; i++)
#pragma unroll
        for (int j = 0; j < 8; j++) acc[i][j] = 0ull;

    // staging registers
    float4 a_r[4];
    float4 b_r[2];
    int arow = tid >> 2;          // A stage: base row, covers +64*it2
    int akq = (tid & 3) * 4;      // A stage: k quad
    int bkr = tid >> 5;           // B stage: base k row, covers +8*i
    int bc4 = (tid & 31) * 4;     // B stage: col quad

#define SG_LOADG(IT)                                                          \
    {                                                                         \
        int k0 = (IT) * 16;                                                   \
        _Pragma("unroll") for (int it2 = 0; it2 < 4; it2++) {                 \
            int gr = n0 + arow + it2 * 64;                                    \
            a_r[it2] = make_float4(0.f, 0.f, 0.f, 0.f);                       \
            if (gr < N)                                                       \
                a_r[it2] = *(const float4*)(A + (size_t)gr * lda + k0 + akq); \
        }                                                                     \
        _Pragma("unroll") for (int i = 0; i < 2; i++) {                       \
            b_r[i] = *(const float4*)(W + (size_t)(k0 + bkr + i * 8) * 128 + bc4); \
        }                                                                     \
    }

#define SG_STORES(BUF)                                                        \
    {                                                                         \
        float* as = As[BUF];                                                  \
        float* bs = Bs[BUF];                                                  \
        _Pragma("unroll") for (int it2 = 0; it2 < 4; it2++) {                 \
            int row = arow + it2 * 64;                                        \
            as[(akq + 0) * 256 + row] = a_r[it2].x;                           \
            as[(akq + 1) * 256 + row] = a_r[it2].y;                           \
            as[(akq + 2) * 256 + row] = a_r[it2].z;                           \
            as[(akq + 3) * 256 + row] = a_r[it2].w;                           \
        }                                                                     \
        _Pragma("unroll") for (int i = 0; i < 2; i++) {                       \
            *(float4*)(bs + (bkr + i * 8) * 128 + bc4) = b_r[i];              \
        }                                                                     \
    }

#define SG_COMPUTE(BUF)                                                       \
    {                                                                         \
        const float* as = As[BUF];                                            \
        const float* bs = Bs[BUF];                                            \
        _Pragma("unroll") for (int k = 0; k < 16; k++) {                      \
            ulonglong2 ap01 = *(const ulonglong2*)(as + k * 256 + tr);        \
            ulonglong2 ap23 = *(const ulonglong2*)(as + k * 256 + tr + 4);    \
            ulonglong2 ap45 = *(const ulonglong2*)(as + k * 256 + tr + 8);    \
            ulonglong2 ap67 = *(const ulonglong2*)(as + k * 256 + tr + 12);   \
            float4 bA = *(const float4*)(bs + k * 128 + tc);                  \
            float4 bB = *(const float4*)(bs + k * 128 + tc + 4);              \
            unsigned long long ap[8] = {ap01.x, ap01.y, ap23.x, ap23.y,       \
                                        ap45.x, ap45.y, ap67.x, ap67.y};      \
            float bf[8] = {bA.x, bA.y, bA.z, bA.w, bB.x, bB.y, bB.z, bB.w};   \
            unsigned long long bd[8];                                         \
            _Pragma("unroll") for (int j = 0; j < 8; j++) {                   \
                unsigned int bi = __float_as_uint(bf[j]);                     \
                asm("mov.b64 %0, {%1, %1};" : "=l"(bd[j]) : "r"(bi));         \
            }                                                                 \
            _Pragma("unroll") for (int ip = 0; ip < 8; ip++) {                \
                _Pragma("unroll") for (int j = 0; j < 8; j++) {               \
                    asm("fma.rn.f32x2 %0, %1, %2, %0;"                        \
                        : "+l"(acc[ip][j]) : "l"(ap[ip]), "l"(bd[j]));        \
                }                                                             \
            }                                                                 \
        }                                                                     \
    }

    int niter = K / 16;
    SG_LOADG(0);
    SG_STORES(0);
    __syncthreads();
    int cur = 0;
    for (int it = 0; it < niter; it++) {
        if (it + 1 < niter) SG_LOADG(it + 1);
        SG_COMPUTE(cur);
        if (it + 1 < niter) {
            SG_STORES(cur ^ 1);
            __syncthreads();
        }
        cur ^= 1;
    }

    // epilogue: acc[ip][j] = (row tr+2ip, row tr+2ip+1) at col tc+j
#pragma unroll
    for (int ip = 0; ip < 8; ip++) {
        int r0 = n0 + tr + 2 * ip;
        float lo[8], hi[8];
#pragma unroll
        for (int j = 0; j < 8; j++) {
            float2 p = *(float2*)&acc[ip][j];
            lo[j] = p.x;
            hi[j] = p.y;
        }
        if (r0 < N) {
            *(float4*)(C + (size_t)r0 * 128 + tc)     = make_float4(lo[0], lo[1], lo[2], lo[3]);
            *(float4*)(C + (size_t)r0 * 128 + tc + 4) = make_float4(lo[4], lo[5], lo[6], lo[7]);
        }
        if (r0 + 1 < N) {
            *(float4*)(C + (size_t)(r0 + 1) * 128 + tc)     = make_float4(hi[0], hi[1], hi[2], hi[3]);
            *(float4*)(C + (size_t)(r0 + 1) * 128 + tc + 4) = make_float4(hi[4], hi[5], hi[6], hi[7]);
        }
    }
#undef SG_LOADG
#undef SG_STORES
#undef SG_COMPUTE
}

// ---------------- aggregate(mean) + bias + self + LayerNorm + ReLU -----------
__global__ void agg_ln_kernel(const float* __restrict__ bn, const float* __restrict__ g,
                              const float* __restrict__ be, int coloff, int N) {
    const float* y = (const float*)d_bufY;
    const float* z = (const float*)d_bufZ;
    float* hout = (float*)d_bufH + coloff;
    int w = (blockIdx.x * blockDim.x + threadIdx.x) >> 5;
    int lane = threadIdx.x & 31;
    if (w >= N) return;
    int s = d_off[w], e = d_off[w + 1];
    float4 acc = make_float4(0.f, 0.f, 0.f, 0.f);
    int i = s;
    for (; i + 4 <= e; i += 4) {
        int s0 = d_csr[i], s1 = d_csr[i + 1], s2 = d_csr[i + 2], s3 = d_csr[i + 3];
        float4 v0 = *(const float4*)(y + (size_t)s0 * 128 + lane * 4);
        float4 v1 = *(const float4*)(y + (size_t)s1 * 128 + lane * 4);
        float4 v2 = *(const float4*)(y + (size_t)s2 * 128 + lane * 4);
        float4 v3 = *(const float4*)(y + (size_t)s3 * 128 + lane * 4);
        acc.x += (v0.x + v1.x) + (v2.x + v3.x);
        acc.y += (v0.y + v1.y) + (v2.y + v3.y);
        acc.z += (v0.z + v1.z) + (v2.z + v3.z);
        acc.w += (v0.w + v1.w) + (v2.w + v3.w);
    }
    for (; i < e; i++) {
        int s0 = d_csr[i];
        float4 v0 = *(const float4*)(y + (size_t)s0 * 128 + lane * 4);
        acc.x += v0.x; acc.y += v0.y; acc.z += v0.z; acc.w += v0.w;
    }
    int deg = e - s;
    float inv = 1.f / (float)(deg > 0 ? deg : 1);
    float4 zb = *(const float4*)(z + (size_t)w * 128 + lane * 4);
    float4 bn4 = *(const float4*)(bn + lane * 4);
    float4 t;
    t.x = fmaf(acc.x, inv, bn4.x + zb.x);
    t.y = fmaf(acc.y, inv, bn4.y + zb.y);
    t.z = fmaf(acc.z, inv, bn4.z + zb.z);
    t.w = fmaf(acc.w, inv, bn4.w + zb.w);
    float sum = t.x + t.y + t.z + t.w;
#pragma unroll
    for (int m = 16; m >= 1; m >>= 1) sum += __shfl_xor_sync(FULLMASK, sum, m);
    float mu = sum * (1.f / 128.f);
    float dx = t.x - mu, dy = t.y - mu, dz = t.z - mu, dw = t.w - mu;
    float sq = dx * dx + dy * dy + dz * dz + dw * dw;
#pragma unroll
    for (int m = 16; m >= 1; m >>= 1) sq += __shfl_xor_sync(FULLMASK, sq, m);
    float r = rsqrtf(sq * (1.f / 128.f) + 1e-5f);
    float4 g4 = *(const float4*)(g + lane * 4);
    float4 be4 = *(const float4*)(be + lane * 4);
    float4 h;
    h.x = fmaxf(fmaf(dx * r, g4.x, be4.x), 0.f);
    h.y = fmaxf(fmaf(dy * r, g4.y, be4.y), 0.f);
    h.z = fmaxf(fmaf(dz * r, g4.z, be4.z), 0.f);
    h.w = fmaxf(fmaf(dw * r, g4.w, be4.w), 0.f);
    *(float4*)(hout + (size_t)w * 256 + lane * 4) = h;
}

// ---------------- head stage A: T = relu(H[N,256] @ Wc[256,32] + bc) ---------
__global__ __launch_bounds__(256) void head_gemm_kernel(int N) {
    __shared__ __align__(16) float As[16 * 260];
    __shared__ __align__(16) float Bs[16 * 32];
    const float* A = (const float*)d_bufH;
    float* T = (float*)d_bufT;
    int n0 = blockIdx.x * 256;
    int tid = threadIdx.x;
    int tr = (tid >> 3) * 8;
    int tc = (tid & 7) * 4;
    unsigned long long acc[8][2];
#pragma unroll
    for (int i = 0; i < 8; i++) { acc[i][0] = 0ull; acc[i][1] = 0ull; }

    for (int k0 = 0; k0 < 256; k0 += 16) {
        __syncthreads();
#pragma unroll
        for (int it = 0; it < 4; it++) {
            int s = tid + it * 256;
            int row = s >> 2;
            int kq = (s & 3) * 4;
            float4 v = make_float4(0.f, 0.f, 0.f, 0.f);
            int gr = n0 + row;
            if (gr < N) v = *(const float4*)(A + (size_t)gr * 256 + k0 + kq);
            As[(kq + 0) * 260 + row] = v.x;
            As[(kq + 1) * 260 + row] = v.y;
            As[(kq + 2) * 260 + row] = v.z;
            As[(kq + 3) * 260 + row] = v.w;
        }
        if (tid < 128) {
            int kr = tid >> 3;
            int c4 = (tid & 7) * 4;
            *(float4*)(Bs + kr * 32 + c4) =
                *(const float4*)((const float*)d_Wc + (k0 + kr) * 32 + c4);
        }
        __syncthreads();
#pragma unroll
        for (int k = 0; k < 16; k++) {
            float4 a0 = *(const float4*)(As + k * 260 + tr);
            float4 a1 = *(const float4*)(As + k * 260 + tr + 4);
            ulonglong2 b0 = *(const ulonglong2*)(Bs + k * 32 + tc);
            float av[8] = {a0.x, a0.y, a0.z, a0.w, a1.x, a1.y, a1.z, a1.w};
#pragma unroll
            for (int i = 0; i < 8; i++) {
                unsigned long long ad;
                unsigned int ai = __float_as_uint(av[i]);
                asm("mov.b64 %0, {%1, %1};" : "=l"(ad) : "r"(ai));
                asm("fma.rn.f32x2 %0, %1, %2, %0;" : "+l"(acc[i][0]) : "l"(ad), "l"(b0.x));
                asm("fma.rn.f32x2 %0, %1, %2, %0;" : "+l"(acc[i][1]) : "l"(ad), "l"(b0.y));
            }
        }
    }
    float4 bcv = *(const float4*)((const float*)d_bc + tc);
#pragma unroll
    for (int i = 0; i < 8; i++) {
        int gr = n0 + tr + i;
        if (gr < N) {
            float2 p0 = *(float2*)&acc[i][0];
            float2 p1 = *(float2*)&acc[i][1];
            float4 o;
            o.x = fmaxf(p0.x + bcv.x, 0.f);
            o.y = fmaxf(p0.y + bcv.y, 0.f);
            o.z = fmaxf(p1.x + bcv.z, 0.f);
            o.w = fmaxf(p1.y + bcv.w, 0.f);
            *(float4*)(T + (size_t)gr * 32 + tc) = o;
        }
    }
}

// ---------------- head stage B: out = T @ W2 + b2 ----------------------------
__global__ void head_out_kernel(const float* __restrict__ W2,
                                const float* __restrict__ b2,
                                float* __restrict__ out, int N) {
    int lane = threadIdx.x & 31;
    float w2r[16];
#pragma unroll
    for (int c4 = 0; c4 < 16; c4 += 4) {
        float4 w = *(const float4*)(W2 + lane * 16 + c4);
        w2r[c4] = w.x; w2r[c4 + 1] = w.y; w2r[c4 + 2] = w.z; w2r[c4 + 3] = w.w;
    }
    float bv = (lane < 16) ? b2[lane] : 0.f;
    int wg = (blockIdx.x * blockDim.x + threadIdx.x) >> 5;
    int nw = (gridDim.x * blockDim.x) >> 5;
    const float* T = (const float*)d_bufT;
    for (int node = wg; node < N; node += nw) {
        float h = T[(size_t)node * 32 + lane];
        float v[16];
#pragma unroll
        for (int c = 0; c < 16; c++) v[c] = h * w2r[c];
#pragma unroll
        for (int c = 0; c < 16; c++) v[c] += __shfl_xor_sync(FULLMASK, v[c], 16);
#pragma unroll
        for (int s = 8; s >= 1; s >>= 1) {
            int up = lane & s;
#pragma unroll
            for (int k = 0; k < 8; k++) {
                if (k < s) {
                    float x = up ? v[k] : v[k + s];
                    x = __shfl_xor_sync(FULLMASK, x, s);
                    v[k] = (up ? v[k + s] : v[k]) + x;
                }
            }
        }
        if (lane < 16) out[(size_t)node * 16 + lane] = v[0] + bv;
    }
}

// ---------------- launch: kernel launches ONLY (graph-capturable) ------------
extern "C" void kernel_launch(void* const* d_in, const int* in_sizes, int n_in,
                              void* d_out, int out_size) {
    const float* x     = (const float*)d_in[0];
    const void*  eiv   = d_in[1];
    const float* W_nl0 = (const float*)d_in[2];
    const float* b_nl0 = (const float*)d_in[3];
    const float* W_r0  = (const float*)d_in[4];
    const float* W_nl1 = (const float*)d_in[5];
    const float* b_nl1 = (const float*)d_in[6];
    const float* W_r1  = (const float*)d_in[7];
    const float* g0    = (const float*)d_in[8];
    const float* be0   = (const float*)d_in[9];
    const float* g1    = (const float*)d_in[10];
    const float* be1   = (const float*)d_in[11];
    const float* W_jk  = (const float*)d_in[12];
    const float* b_jk  = (const float*)d_in[13];
    const float* W_h1  = (const float*)d_in[14];
    const float* b_h1  = (const float*)d_in[15];
    const float* W_h2  = (const float*)d_in[16];
    const float* b_h2  = (const float*)d_in[17];
    float* out = (float*)d_out;

    int N = in_sizes[0] / 256;
    int E = in_sizes[1] / 2;
    if (N > NN) N = NN;
    if (E > NE) E = NE;

    int gN = (N + 255) / 256;
    int gE = (E + 255) / 256;
    int gG = (N + 255) / 256;
    int gAgg = (N + 7) / 8;
    int gScan = (N + 1023) / 1024;

    dim3 gPair(gG, 1, 2);

    detect_dtype_kernel<<<1, 256>>>((const int*)eiv, in_sizes[1]);
    zero_deg_kernel<<<gN, 256>>>(N);
    count_deg_kernel<<<gE, 256>>>(eiv, E, N);
    scan_local_kernel<<<gScan, 1024>>>(N);
    scan_part_kernel<<<1, 128>>>(gScan, N);
    sgemm256_kernel<<<gPair, 256>>>(x, 256, 256, W_nl0, W_r0, 0, 1, N);
    scan_add_kernel<<<gScan, 1024>>>(N);
    fill_csr_kernel<<<gE, 256>>>(eiv, E, N);
    fold_w_kernel<<<32, 256>>>(W_jk, W_h1, b_jk, b_h1);

    agg_ln_kernel<<<gAgg, 256>>>(b_nl0, g0, be0, 0, N);

    sgemm256_kernel<<<gPair, 256>>>(nullptr, 256, 128, W_nl1, W_r1, 0, 1, N);
    agg_ln_kernel<<<gAgg, 256>>>(b_nl1, g1, be1, 128, N);

    head_gemm_kernel<<<gG, 256>>>(N);
    head_out_kernel<<<296, 256>>>(W_h2, b_h2, out, N);
}